// round 16
// baseline (speedup 1.0000x reference)
#include <cuda_runtime.h>
#include <cuda_bf16.h>
#include <cuda_fp16.h>

#define N_NODES 100000
#define N_EDGES 1600000
#define DIM 128
#define HID 256
#define SCAN_B 98

typedef unsigned long long u64;
typedef unsigned int u32;

// ---------------- scratch (static device globals; no allocs allowed) --------
__device__ float g_deg[N_NODES];
__device__ int   g_cnt[N_NODES];
__device__ int   g_part[SCAN_B];
__device__ int   g_ctr;
__device__ int   g_row[N_NODES + 1];
__device__ int   g_fill[N_NODES];
__device__ int2  g_csr[N_EDGES];
__device__ __half g_h16a[N_NODES * DIM];
__device__ __half g_h16b[N_NODES * DIM];
__device__ float g_ha[N_NODES * DIM];
__device__ __nv_bfloat16 g_w1h[HID * DIM], g_w1l[HID * DIM];
__device__ __nv_bfloat16 g_w2h[DIM * HID], g_w2l[DIM * HID];
__device__ int   g_sh;

// ---------------- warp-MMA helpers ------------------------------------------
__device__ __forceinline__ u32 smem_u32(const void* p) {
    u32 a;
    asm("{ .reg .u64 t; cvta.to.shared.u64 t, %1; cvt.u32.u64 %0, t; }" : "=r"(a) : "l"(p));
    return a;
}
__device__ __forceinline__ void ldsm4(u32* r, u32 a) {
    asm volatile("ldmatrix.sync.aligned.m8n8.x4.shared.b16 {%0,%1,%2,%3}, [%4];"
                 : "=r"(r[0]), "=r"(r[1]), "=r"(r[2]), "=r"(r[3]) : "r"(a));
}
__device__ __forceinline__ void mma16816(float* c, const u32* a, const u32* b) {
    asm volatile("mma.sync.aligned.m16n8k16.row.col.f32.bf16.bf16.f32 "
                 "{%0,%1,%2,%3}, {%4,%5,%6,%7}, {%8,%9}, {%0,%1,%2,%3};"
                 : "+f"(c[0]), "+f"(c[1]), "+f"(c[2]), "+f"(c[3])
                 : "r"(a[0]), "r"(a[1]), "r"(a[2]), "r"(a[3]), "r"(b[0]), "r"(b[1]));
}
__device__ __forceinline__ void bsplit(float v, __nv_bfloat16& hi, __nv_bfloat16& lo) {
    hi = __float2bfloat16(v);
    lo = __float2bfloat16(v - __bfloat162float(hi));
}

// ---------------- init: zero deg/cnt/ctr + detect + weight split -------------
__global__ void init_kernel(const int* __restrict__ src,
                            const float* __restrict__ w1, const float* __restrict__ w2) {
    int i = blockIdx.x * blockDim.x + threadIdx.x;
    if (i < N_NODES) { g_deg[i] = 0.f; g_cnt[i] = 0; }
    if (i == 0) {
        g_sh = (src[1] == 0 && src[2] == 1) ? 1 : 0;
        g_ctr = 0;
    }
    if (i < HID * DIM) {
        bsplit(w1[i], g_w1h[i], g_w1l[i]);
        bsplit(w2[i], g_w2h[i], g_w2l[i]);
    }
}

__global__ void deg_hist_kernel(const int* __restrict__ src, const int* __restrict__ dst) {
    int e = blockIdx.x * blockDim.x + threadIdx.x;
    if (e < N_EDGES) {
        int sh = g_sh;
        atomicAdd(&g_deg[src[(long)e << sh]], 1.0f);
        atomicAdd(&g_cnt[dst[(long)e << sh]], 1);
    }
}

// fused scan: per-block inclusive scan + cross-block barrier via atomic counter.
// 98 blocks (< 148 SMs) => all co-resident, spin is deadlock-free.
__global__ void scan_kernel() {
    __shared__ int s[1024];
    __shared__ int base_s;
    int t = threadIdx.x;
    int b = blockIdx.x;
    int i = b * 1024 + t;
    int v = (i < N_NODES) ? g_cnt[i] : 0;
    s[t] = v;
    __syncthreads();
    for (int off = 1; off < 1024; off <<= 1) {
        int add = (t >= off) ? s[t - off] : 0;
        __syncthreads();
        s[t] += add;
        __syncthreads();
    }
    if (t == 0) {
        g_part[b] = s[1023];
        __threadfence();
        atomicAdd(&g_ctr, 1);
        while (*(volatile int*)&g_ctr < SCAN_B) {}
        __threadfence();
        int base = 0;
        for (int k = 0; k < b; k++) base += g_part[k];
        base_s = base;
    }
    __syncthreads();
    int base = base_s;
    if (i < N_NODES) {
        int excl = base + s[t] - v;
        g_row[i] = excl;
        g_fill[i] = excl;
        if (i == N_NODES - 1) g_row[N_NODES] = base + s[t];
    }
}

__global__ void fill_kernel(const int* __restrict__ src, const int* __restrict__ dst) {
    int e = blockIdx.x * blockDim.x + threadIdx.x;
    if (e < N_EDGES) {
        int sh = g_sh;
        int s = src[(long)e << sh];
        int d = dst[(long)e << sh];
        float c = rsqrtf(g_deg[s] * g_deg[d]);
        int pos = atomicAdd(&g_fill[d], 1);
        g_csr[pos] = make_int2(s, __float_as_int(c));
    }
}

// ---------------- forward rotation -> fp16 rows -------------------------------
__global__ void rot_kernel(const float* __restrict__ x, const float* __restrict__ rep,
                           __half* __restrict__ out16) {
    int i = blockIdx.x * blockDim.x + threadIdx.x;
    int n = i >> 7;
    int t = i & 127;
    int b = t >> 4, c = (t >> 2) & 3, el = t & 3;
    float4 r = *(const float4*)(rep + (((long)n * 8 + b) * 16 + c * 4));
    const float* xb = x + (long)n * DIM + b * 16 + el;
    float v = r.x * xb[0] + r.y * xb[4] + r.z * xb[8] + r.w * xb[12];
    out16[i] = __float2half(v);
}

// ---------------- gathers: half-warp edge pairing, uint4 row loads ------------
// Lanes 0-15 handle edge e, lanes 16-31 edge e+1; each lane owns 8 half-cols.
__device__ __forceinline__ void acc8(float* acc, uint4 v, float f) {
    float2 a = __half22float2(*(__half2*)&v.x);
    float2 b = __half22float2(*(__half2*)&v.y);
    float2 c = __half22float2(*(__half2*)&v.z);
    float2 d = __half22float2(*(__half2*)&v.w);
    acc[0] += a.x * f; acc[1] += a.y * f;
    acc[2] += b.x * f; acc[3] += b.y * f;
    acc[4] += c.x * f; acc[5] += c.y * f;
    acc[6] += d.x * f; acc[7] += d.y * f;
}

__device__ __forceinline__ void gather_core(const __half* __restrict__ hin,
                                            int n, int half, int sl, float acc[8]) {
    int beg = g_row[n], end = g_row[n + 1];
#pragma unroll
    for (int k = 0; k < 8; k++) acc[k] = 0.f;
    int e = beg;
    for (; e + 4 <= end; e += 4) {
        int2 c0 = g_csr[e + half];
        int2 c1 = g_csr[e + 2 + half];
        uint4 v0 = __ldg((const uint4*)(hin + (long)c0.x * DIM) + sl);
        uint4 v1 = __ldg((const uint4*)(hin + (long)c1.x * DIM) + sl);
        acc8(acc, v0, __int_as_float(c0.y));
        acc8(acc, v1, __int_as_float(c1.y));
    }
    if (e + 2 <= end) {
        int2 c0 = g_csr[e + half];
        uint4 v0 = __ldg((const uint4*)(hin + (long)c0.x * DIM) + sl);
        acc8(acc, v0, __int_as_float(c0.y));
        e += 2;
    }
    if (e < end && half == 0) {
        int2 c0 = g_csr[e];
        uint4 v0 = __ldg((const uint4*)(hin + (long)c0.x * DIM) + sl);
        acc8(acc, v0, __int_as_float(c0.y));
    }
    // combine half-warps
#pragma unroll
    for (int k = 0; k < 8; k++)
        acc[k] += __shfl_xor_sync(0xFFFFFFFFu, acc[k], 16);
}

// hop 1: fp16 -> fp16
__global__ void gather_h2h(const __half* __restrict__ hin, __half* __restrict__ hout) {
    int gid = blockIdx.x * blockDim.x + threadIdx.x;
    int n = gid >> 5;
    int lane = gid & 31;
    int half = lane >> 4, sl = lane & 15;
    float acc[8];
    gather_core(hin, n, half, sl, acc);
    int cb = half * 4;
    __half2 p0 = __floats2half2_rn(acc[cb + 0], acc[cb + 1]);
    __half2 p1 = __floats2half2_rn(acc[cb + 2], acc[cb + 3]);
    uint2 o = make_uint2(*(u32*)&p0, *(u32*)&p1);
    *(uint2*)(hout + (long)n * DIM + sl * 8 + half * 4) = o;
}

// hop 2: fp16 -> fp32 (feeds FFN)
__global__ void gather_h2f(const __half* __restrict__ hin, float* __restrict__ hout) {
    int gid = blockIdx.x * blockDim.x + threadIdx.x;
    int n = gid >> 5;
    int lane = gid & 31;
    int half = lane >> 4, sl = lane & 15;
    float acc[8];
    gather_core(hin, n, half, sl, acc);
    int cb = half * 4;
    *(float4*)(hout + (long)n * DIM + sl * 8 + half * 4) =
        make_float4(acc[cb + 0], acc[cb + 1], acc[cb + 2], acc[cb + 3]);
}

// ---------------- fused FFN (HMMA): out = (gelu(rot_t(h)@w1^T+b1))@w2^T+b2 ----
#define P1   136
#define PB1  40
#define P2   264
#define PB2  72
#define RA_SZ (64 * P2 * 2 * 2)                    // 67,584 B
#define A1_HI 0
#define A1_LO (64 * P1 * 2)
#define H_HI  0
#define H_LO  (64 * P2 * 2)
#define RB    RA_SZ
#define B1_HI (RB)
#define B1_LO (RB + 256 * PB1 * 2)
#define B2_HI (RB)
#define B2_LO (RB + 128 * PB2 * 2)
#define FF_SMEM (RA_SZ + 2 * 256 * PB1 * 2)        // 108,544 B
__global__ void __launch_bounds__(256, 2) ffn_fused(const float* __restrict__ rep,
                                                    const float* __restrict__ b1,
                                                    const float* __restrict__ b2,
                                                    float* __restrict__ out) {
    extern __shared__ char smem[];
    u32 sb = smem_u32(smem);
    int tid = threadIdx.x;
    int wid = tid >> 5, lane = tid & 31;
    int wg = wid & 3, jh = wid >> 2;
    long nbase = (long)blockIdx.x * 64;

    // ---- stage A1: rot_t(g_ha) split to hi/lo (64 rows, full K=128) ----
    for (int idx = tid; idx < 64 * 16; idx += 256) {
        int row = idx >> 4, u = idx & 15;
        long n = nbase + row; if (n >= N_NODES) n = N_NODES - 1;
        int b = u >> 1;
        const float4* hv = (const float4*)(g_ha + n * DIM + b * 16);
        float4 q0 = hv[0], q1 = hv[1], q2 = hv[2], q3 = hv[3];
        const float4* rv = (const float4*)(rep + ((long)n * 8 + b) * 16);
        float4 R0 = rv[0], R1 = rv[1], R2 = rv[2], R3 = rv[3];
        float rc[2][4];
        if (u & 1) {
            rc[0][0] = R0.z; rc[0][1] = R1.z; rc[0][2] = R2.z; rc[0][3] = R3.z;
            rc[1][0] = R0.w; rc[1][1] = R1.w; rc[1][2] = R2.w; rc[1][3] = R3.w;
        } else {
            rc[0][0] = R0.x; rc[0][1] = R1.x; rc[0][2] = R2.x; rc[0][3] = R3.x;
            rc[1][0] = R0.y; rc[1][1] = R1.y; rc[1][2] = R2.y; rc[1][3] = R3.y;
        }
        __nv_bfloat16 hi[8], lo[8];
#pragma unroll
        for (int cc = 0; cc < 2; cc++) {
            float v0 = rc[cc][0] * q0.x + rc[cc][1] * q1.x + rc[cc][2] * q2.x + rc[cc][3] * q3.x;
            float v1 = rc[cc][0] * q0.y + rc[cc][1] * q1.y + rc[cc][2] * q2.y + rc[cc][3] * q3.y;
            float v2 = rc[cc][0] * q0.z + rc[cc][1] * q1.z + rc[cc][2] * q2.z + rc[cc][3] * q3.z;
            float v3 = rc[cc][0] * q0.w + rc[cc][1] * q1.w + rc[cc][2] * q2.w + rc[cc][3] * q3.w;
            bsplit(v0, hi[cc * 4 + 0], lo[cc * 4 + 0]);
            bsplit(v1, hi[cc * 4 + 1], lo[cc * 4 + 1]);
            bsplit(v2, hi[cc * 4 + 2], lo[cc * 4 + 2]);
            bsplit(v3, hi[cc * 4 + 3], lo[cc * 4 + 3]);
        }
        *(uint4*)(smem + A1_HI + (row * P1 + u * 8) * 2) = *(uint4*)hi;
        *(uint4*)(smem + A1_LO + (row * P1 + u * 8) * 2) = *(uint4*)lo;
    }

    // ---- layer 1 MMAs: 4 chunks of K=32 ----
    u32 a_row = (u32)(wg * 16 + (lane & 15));
    u32 a_col = (u32)((lane >> 4) * 8);
    u32 aH = sb + A1_HI + (a_row * P1 + a_col) * 2;
    u32 aL = sb + A1_LO + (a_row * P1 + a_col) * 2;
    int g = lane >> 3;
    u32 brow = (u32)(jh * 128 + (g >> 1) * 8 + (lane & 7));
    u32 bcol = (u32)((g & 1) * 8);
    u32 bH4 = sb + B1_HI + (brow * PB1 + bcol) * 2;
    u32 bL4 = sb + B1_LO + (brow * PB1 + bcol) * 2;

    float bj1v[16][2];
#pragma unroll
    for (int jt = 0; jt < 16; jt++) {
        int jg = jh * 128 + jt * 8 + (lane & 3) * 2;
        bj1v[jt][0] = __ldg(&b1[jg]);
        bj1v[jt][1] = __ldg(&b1[jg + 1]);
    }

    float acc[16][4];
#pragma unroll
    for (int t = 0; t < 16; t++)
#pragma unroll
        for (int q = 0; q < 4; q++) acc[t][q] = 0.f;

#pragma unroll
    for (int kc = 0; kc < 4; kc++) {
        for (int idx = tid; idx < 256 * 4; idx += 256) {
            int row = idx >> 2, u = idx & 3;
            long koff = kc * 32 + u * 8;
            *(uint4*)(smem + B1_HI + (row * PB1 + u * 8) * 2) = *(const uint4*)(g_w1h + (long)row * DIM + koff);
            *(uint4*)(smem + B1_LO + (row * PB1 + u * 8) * 2) = *(const uint4*)(g_w1l + (long)row * DIM + koff);
        }
        __syncthreads();
#pragma unroll
        for (int ks = 0; ks < 2; ks++) {
            u32 ah[4], al[4];
            ldsm4(ah, aH + kc * 64 + ks * 32);
            ldsm4(al, aL + kc * 64 + ks * 32);
#pragma unroll
            for (int jp = 0; jp < 8; jp++) {
                u32 bh[4], bl[4];
                ldsm4(bh, bH4 + jp * (16 * PB1 * 2) + ks * 32);
                ldsm4(bl, bL4 + jp * (16 * PB1 * 2) + ks * 32);
                mma16816(acc[2 * jp],     ah, &bh[0]);
                mma16816(acc[2 * jp],     ah, &bl[0]);
                mma16816(acc[2 * jp],     al, &bh[0]);
                mma16816(acc[2 * jp + 1], ah, &bh[2]);
                mma16816(acc[2 * jp + 1], ah, &bl[2]);
                mma16816(acc[2 * jp + 1], al, &bh[2]);
            }
        }
        __syncthreads();
    }

    // ---- layer 1 epilogue: bias + GELU, split, write hid tile to smem ----
    {
        int r0 = wg * 16 + (lane >> 2);
        int r1 = r0 + 8;
#pragma unroll
        for (int jt = 0; jt < 16; jt++) {
            int jg = jh * 128 + jt * 8 + (lane & 3) * 2;
#pragma unroll
            for (int half = 0; half < 2; half++) {
                int r = half ? r1 : r0;
                float a0 = acc[jt][half * 2 + 0] + bj1v[jt][0];
                float a1 = acc[jt][half * 2 + 1] + bj1v[jt][1];
                float y0 = 0.5f * a0 * (1.0f + erff(a0 * 0.7071067811865476f));
                float y1 = 0.5f * a1 * (1.0f + erff(a1 * 0.7071067811865476f));
                __nv_bfloat162 ph, pl;
                bsplit(y0, ph.x, pl.x);
                bsplit(y1, ph.y, pl.y);
                *(u32*)(smem + H_HI + (r * P2 + jg) * 2) = *(u32*)&ph;
                *(u32*)(smem + H_LO + (r * P2 + jg) * 2) = *(u32*)&pl;
            }
        }
    }
    __syncthreads();

    // ---- layer 2 MMAs: 4 chunks of K=64 ----
    u32 aH2 = sb + H_HI + (a_row * P2 + a_col) * 2;
    u32 aL2 = sb + H_LO + (a_row * P2 + a_col) * 2;
    u32 brow2 = (u32)(jh * 64 + (g >> 1) * 8 + (lane & 7));
    u32 bH2 = sb + B2_HI + (brow2 * PB2 + bcol) * 2;
    u32 bL2 = sb + B2_LO + (brow2 * PB2 + bcol) * 2;

    float acc2[8][4];
#pragma unroll
    for (int t = 0; t < 8; t++)
#pragma unroll
        for (int q = 0; q < 4; q++) acc2[t][q] = 0.f;

#pragma unroll
    for (int kc = 0; kc < 4; kc++) {
        for (int idx = tid; idx < 128 * 8; idx += 256) {
            int row = idx >> 3, u = idx & 7;
            long koff = kc * 64 + u * 8;
            *(uint4*)(smem + B2_HI + (row * PB2 + u * 8) * 2) = *(const uint4*)(g_w2h + (long)row * HID + koff);
            *(uint4*)(smem + B2_LO + (row * PB2 + u * 8) * 2) = *(const uint4*)(g_w2l + (long)row * HID + koff);
        }
        __syncthreads();
#pragma unroll
        for (int ks = 0; ks < 4; ks++) {
            u32 ah[4], al[4];
            ldsm4(ah, aH2 + kc * 128 + ks * 32);
            ldsm4(al, aL2 + kc * 128 + ks * 32);
#pragma unroll
            for (int jp = 0; jp < 4; jp++) {
                u32 bh[4], bl[4];
                ldsm4(bh, bH2 + jp * (16 * PB2 * 2) + ks * 32);
                ldsm4(bl, bL2 + jp * (16 * PB2 * 2) + ks * 32);
                mma16816(acc2[2 * jp],     ah, &bh[0]);
                mma16816(acc2[2 * jp],     ah, &bl[0]);
                mma16816(acc2[2 * jp],     al, &bh[0]);
                mma16816(acc2[2 * jp + 1], ah, &bh[2]);
                mma16816(acc2[2 * jp + 1], ah, &bl[2]);
                mma16816(acc2[2 * jp + 1], al, &bh[2]);
            }
        }
        __syncthreads();
    }

    // ---- layer 2 epilogue: bias, store out ----
    long n0 = nbase + wg * 16 + (lane >> 2);
    long n1 = n0 + 8;
#pragma unroll
    for (int jt = 0; jt < 8; jt++) {
        int jg = jh * 64 + jt * 8 + (lane & 3) * 2;
        float bj0 = __ldg(&b2[jg]), bj1 = __ldg(&b2[jg + 1]);
        if (n0 < N_NODES) {
            float2 v = make_float2(acc2[jt][0] + bj0, acc2[jt][1] + bj1);
            *(float2*)(out + n0 * DIM + jg) = v;
        }
        if (n1 < N_NODES) {
            float2 v = make_float2(acc2[jt][2] + bj0, acc2[jt][3] + bj1);
            *(float2*)(out + n1 * DIM + jg) = v;
        }
    }
}

// ---------------- launch ----------------------------------------------------
extern "C" void kernel_launch(void* const* d_in, const int* in_sizes, int n_in,
                              void* d_out, int out_size) {
    const float* x   = (const float*)d_in[0];
    const float* rep = (const float*)d_in[1];
    const int*   src = (const int*)d_in[2];
    const int*   dst = (const int*)d_in[3];
    const float* w1  = (const float*)d_in[4];
    const float* b1  = (const float*)d_in[5];
    const float* w2  = (const float*)d_in[6];
    const float* b2  = (const float*)d_in[7];
    float* out = (float*)d_out;

    static int smem_set = 0;
    if (!smem_set) {
        cudaFuncSetAttribute(ffn_fused, cudaFuncAttributeMaxDynamicSharedMemorySize, FF_SMEM);
        smem_set = 1;
    }

    float* ha;
    __half *h16a, *h16b;
    cudaGetSymbolAddress((void**)&ha,   g_ha);
    cudaGetSymbolAddress((void**)&h16a, g_h16a);
    cudaGetSymbolAddress((void**)&h16b, g_h16b);

    // CSR build (fused scan)
    init_kernel<<<(N_NODES + 255) / 256, 256>>>(src, w1, w2);
    deg_hist_kernel<<<N_EDGES / 256, 256>>>(src, dst);
    scan_kernel<<<SCAN_B, 1024>>>();
    fill_kernel<<<N_EDGES / 256, 256>>>(src, dst);

    // forward rotation x -> fp16 rows
    rot_kernel<<<(N_NODES * DIM) / 256, 256>>>(x, rep, h16a);

    // message passing: h16a -> h16b (fp16) -> g_ha (fp32)
    gather_h2h<<<(N_NODES * 32) / 256, 256>>>(h16a, h16b);
    gather_h2f<<<(N_NODES * 32) / 256, 256>>>(h16b, ha);

    // fused FFN (rot_t + layer1 + gelu + layer2, hid never leaves smem)
    ffn_fused<<<(N_NODES + 63) / 64, 256, FF_SMEM>>>(rep, b1, b2, out);
}

// round 17
// speedup vs baseline: 1.0710x; 1.0710x over previous
#include <cuda_runtime.h>
#include <cuda_bf16.h>
#include <cuda_fp16.h>

#define N_NODES 100000
#define N_EDGES 1600000
#define DIM 128
#define HID 256
#define SCAN_B 98

typedef unsigned long long u64;
typedef unsigned int u32;

// ---------------- scratch (static device globals; no allocs allowed) --------
__device__ float g_deg[N_NODES];
__device__ int   g_cnt[N_NODES];
__device__ int   g_part[SCAN_B];
__device__ int   g_ctr;
__device__ int   g_row[N_NODES + 1];
__device__ int   g_fill[N_NODES];
__device__ int   g_csr[N_EDGES];          // src index only (coef factorized out)
__device__ __half g_h16a[N_NODES * DIM];
__device__ __half g_h16b[N_NODES * DIM];
__device__ float g_ha[N_NODES * DIM];
__device__ __nv_bfloat16 g_w1h[HID * DIM], g_w1l[HID * DIM];
__device__ __nv_bfloat16 g_w2h[DIM * HID], g_w2l[DIM * HID];
__device__ int   g_sh;

// ---------------- warp-MMA helpers ------------------------------------------
__device__ __forceinline__ u32 smem_u32(const void* p) {
    u32 a;
    asm("{ .reg .u64 t; cvta.to.shared.u64 t, %1; cvt.u32.u64 %0, t; }" : "=r"(a) : "l"(p));
    return a;
}
__device__ __forceinline__ void ldsm4(u32* r, u32 a) {
    asm volatile("ldmatrix.sync.aligned.m8n8.x4.shared.b16 {%0,%1,%2,%3}, [%4];"
                 : "=r"(r[0]), "=r"(r[1]), "=r"(r[2]), "=r"(r[3]) : "r"(a));
}
__device__ __forceinline__ void mma16816(float* c, const u32* a, const u32* b) {
    asm volatile("mma.sync.aligned.m16n8k16.row.col.f32.bf16.bf16.f32 "
                 "{%0,%1,%2,%3}, {%4,%5,%6,%7}, {%8,%9}, {%0,%1,%2,%3};"
                 : "+f"(c[0]), "+f"(c[1]), "+f"(c[2]), "+f"(c[3])
                 : "r"(a[0]), "r"(a[1]), "r"(a[2]), "r"(a[3]), "r"(b[0]), "r"(b[1]));
}
__device__ __forceinline__ void bsplit(float v, __nv_bfloat16& hi, __nv_bfloat16& lo) {
    hi = __float2bfloat16(v);
    lo = __float2bfloat16(v - __bfloat162float(hi));
}

// ---------------- init: zero deg/cnt/ctr + detect + weight split -------------
__global__ void init_kernel(const int* __restrict__ src,
                            const float* __restrict__ w1, const float* __restrict__ w2) {
    int i = blockIdx.x * blockDim.x + threadIdx.x;
    if (i < N_NODES) { g_deg[i] = 0.f; g_cnt[i] = 0; }
    if (i == 0) {
        g_sh = (src[1] == 0 && src[2] == 1) ? 1 : 0;
        g_ctr = 0;
    }
    if (i < HID * DIM) {
        bsplit(w1[i], g_w1h[i], g_w1l[i]);
        bsplit(w2[i], g_w2h[i], g_w2l[i]);
    }
}

__global__ void deg_hist_kernel(const int* __restrict__ src, const int* __restrict__ dst) {
    int e = blockIdx.x * blockDim.x + threadIdx.x;
    if (e < N_EDGES) {
        int sh = g_sh;
        atomicAdd(&g_deg[src[(long)e << sh]], 1.0f);
        atomicAdd(&g_cnt[dst[(long)e << sh]], 1);
    }
}

// fused scan: per-block inclusive scan + cross-block barrier via atomic counter.
__global__ void scan_kernel() {
    __shared__ int s[1024];
    __shared__ int base_s;
    int t = threadIdx.x;
    int b = blockIdx.x;
    int i = b * 1024 + t;
    int v = (i < N_NODES) ? g_cnt[i] : 0;
    s[t] = v;
    __syncthreads();
    for (int off = 1; off < 1024; off <<= 1) {
        int add = (t >= off) ? s[t - off] : 0;
        __syncthreads();
        s[t] += add;
        __syncthreads();
    }
    if (t == 0) {
        g_part[b] = s[1023];
        __threadfence();
        atomicAdd(&g_ctr, 1);
        while (*(volatile int*)&g_ctr < SCAN_B) {}
        __threadfence();
        int base = 0;
        for (int k = 0; k < b; k++) base += g_part[k];
        base_s = base;
    }
    __syncthreads();
    int base = base_s;
    if (i < N_NODES) {
        int excl = base + s[t] - v;
        g_row[i] = excl;
        g_fill[i] = excl;
        if (i == N_NODES - 1) g_row[N_NODES] = base + s[t];
    }
}

// fill CSR: src index only (4B/edge)
__global__ void fill_kernel(const int* __restrict__ src, const int* __restrict__ dst) {
    int e = blockIdx.x * blockDim.x + threadIdx.x;
    if (e < N_EDGES) {
        int sh = g_sh;
        int s = src[(long)e << sh];
        int d = dst[(long)e << sh];
        int pos = atomicAdd(&g_fill[d], 1);
        g_csr[pos] = s;
    }
}

// ---------------- forward rotation, pre-scaled by rsq(deg) -> fp16 -----------
__global__ void rot_kernel(const float* __restrict__ x, const float* __restrict__ rep,
                           __half* __restrict__ out16) {
    int i = blockIdx.x * blockDim.x + threadIdx.x;
    int n = i >> 7;
    int t = i & 127;
    int b = t >> 4, c = (t >> 2) & 3, el = t & 3;
    float rs = rsqrtf(__ldg(&g_deg[n]));
    float4 r = *(const float4*)(rep + (((long)n * 8 + b) * 16 + c * 4));
    const float* xb = x + (long)n * DIM + b * 16 + el;
    float v = r.x * xb[0] + r.y * xb[4] + r.z * xb[8] + r.w * xb[12];
    out16[i] = __float2half(v * rs);
}

// ---------------- gathers: plain sums, scales folded at boundaries ------------
__device__ __forceinline__ void gather_core(const __half* __restrict__ hin,
                                            int n, int lane, float acc[4]) {
    int beg = g_row[n], end = g_row[n + 1];
    acc[0] = acc[1] = acc[2] = acc[3] = 0.f;
    int e = beg;
    for (; e + 4 <= end; e += 4) {
        int s0 = g_csr[e],     s1 = g_csr[e + 1];
        int s2 = g_csr[e + 2], s3 = g_csr[e + 3];
        uint2 v0 = __ldg((const uint2*)(hin + (long)s0 * DIM) + lane);
        uint2 v1 = __ldg((const uint2*)(hin + (long)s1 * DIM) + lane);
        uint2 v2 = __ldg((const uint2*)(hin + (long)s2 * DIM) + lane);
        uint2 v3 = __ldg((const uint2*)(hin + (long)s3 * DIM) + lane);
        float2 a0 = __half22float2(*(__half2*)&v0.x), b0 = __half22float2(*(__half2*)&v0.y);
        float2 a1 = __half22float2(*(__half2*)&v1.x), b1 = __half22float2(*(__half2*)&v1.y);
        float2 a2 = __half22float2(*(__half2*)&v2.x), b2 = __half22float2(*(__half2*)&v2.y);
        float2 a3 = __half22float2(*(__half2*)&v3.x), b3 = __half22float2(*(__half2*)&v3.y);
        acc[0] += a0.x + a1.x + a2.x + a3.x;
        acc[1] += a0.y + a1.y + a2.y + a3.y;
        acc[2] += b0.x + b1.x + b2.x + b3.x;
        acc[3] += b0.y + b1.y + b2.y + b3.y;
    }
    for (; e < end; e++) {
        int s0 = g_csr[e];
        uint2 v0 = __ldg((const uint2*)(hin + (long)s0 * DIM) + lane);
        float2 a0 = __half22float2(*(__half2*)&v0.x), b0 = __half22float2(*(__half2*)&v0.y);
        acc[0] += a0.x; acc[1] += a0.y; acc[2] += b0.x; acc[3] += b0.y;
    }
}

// hop 1: out = (1/deg[d]) * sum  (== rsq[d]^2: this hop's post-scale and the
// next hop's pre-scale combined), stored fp16
__global__ void gather_h2h(const __half* __restrict__ hin, __half* __restrict__ hout) {
    int gid = blockIdx.x * blockDim.x + threadIdx.x;
    int n = gid >> 5;
    int lane = gid & 31;
    float acc[4];
    gather_core(hin, n, lane, acc);
    float sc = 1.0f / __ldg(&g_deg[n]);
    __half2 o0 = __floats2half2_rn(acc[0] * sc, acc[1] * sc);
    __half2 o1 = __floats2half2_rn(acc[2] * sc, acc[3] * sc);
    uint2 o = make_uint2(*(u32*)&o0, *(u32*)&o1);
    ((uint2*)(hout + (long)n * DIM))[lane] = o;
}

// hop 2: out = rsq(deg[d]) * sum, fp32 (feeds FFN)
__global__ void gather_h2f(const __half* __restrict__ hin, float* __restrict__ hout) {
    int gid = blockIdx.x * blockDim.x + threadIdx.x;
    int n = gid >> 5;
    int lane = gid & 31;
    float acc[4];
    gather_core(hin, n, lane, acc);
    float sc = rsqrtf(__ldg(&g_deg[n]));
    *(float4*)(hout + (long)n * DIM + lane * 4) =
        make_float4(acc[0] * sc, acc[1] * sc, acc[2] * sc, acc[3] * sc);
}

// ---------------- fused FFN (HMMA): out = (gelu(rot_t(h)@w1^T+b1))@w2^T+b2 ----
#define P1   136
#define PB1  40
#define P2   264
#define PB2  72
#define RA_SZ (64 * P2 * 2 * 2)                    // 67,584 B
#define A1_HI 0
#define A1_LO (64 * P1 * 2)
#define H_HI  0
#define H_LO  (64 * P2 * 2)
#define RB    RA_SZ
#define B1_HI (RB)
#define B1_LO (RB + 256 * PB1 * 2)
#define B2_HI (RB)
#define B2_LO (RB + 128 * PB2 * 2)
#define FF_SMEM (RA_SZ + 2 * 256 * PB1 * 2)        // 108,544 B
__global__ void __launch_bounds__(256, 2) ffn_fused(const float* __restrict__ rep,
                                                    const float* __restrict__ b1,
                                                    const float* __restrict__ b2,
                                                    float* __restrict__ out) {
    extern __shared__ char smem[];
    u32 sb = smem_u32(smem);
    int tid = threadIdx.x;
    int wid = tid >> 5, lane = tid & 31;
    int wg = wid & 3, jh = wid >> 2;
    long nbase = (long)blockIdx.x * 64;

    // ---- stage A1: rot_t(g_ha) split to hi/lo (64 rows, full K=128) ----
    for (int idx = tid; idx < 64 * 16; idx += 256) {
        int row = idx >> 4, u = idx & 15;
        long n = nbase + row; if (n >= N_NODES) n = N_NODES - 1;
        int b = u >> 1;
        const float4* hv = (const float4*)(g_ha + n * DIM + b * 16);
        float4 q0 = hv[0], q1 = hv[1], q2 = hv[2], q3 = hv[3];
        const float4* rv = (const float4*)(rep + ((long)n * 8 + b) * 16);
        float4 R0 = rv[0], R1 = rv[1], R2 = rv[2], R3 = rv[3];
        float rc[2][4];
        if (u & 1) {
            rc[0][0] = R0.z; rc[0][1] = R1.z; rc[0][2] = R2.z; rc[0][3] = R3.z;
            rc[1][0] = R0.w; rc[1][1] = R1.w; rc[1][2] = R2.w; rc[1][3] = R3.w;
        } else {
            rc[0][0] = R0.x; rc[0][1] = R1.x; rc[0][2] = R2.x; rc[0][3] = R3.x;
            rc[1][0] = R0.y; rc[1][1] = R1.y; rc[1][2] = R2.y; rc[1][3] = R3.y;
        }
        __nv_bfloat16 hi[8], lo[8];
#pragma unroll
        for (int cc = 0; cc < 2; cc++) {
            float v0 = rc[cc][0] * q0.x + rc[cc][1] * q1.x + rc[cc][2] * q2.x + rc[cc][3] * q3.x;
            float v1 = rc[cc][0] * q0.y + rc[cc][1] * q1.y + rc[cc][2] * q2.y + rc[cc][3] * q3.y;
            float v2 = rc[cc][0] * q0.z + rc[cc][1] * q1.z + rc[cc][2] * q2.z + rc[cc][3] * q3.z;
            float v3 = rc[cc][0] * q0.w + rc[cc][1] * q1.w + rc[cc][2] * q2.w + rc[cc][3] * q3.w;
            bsplit(v0, hi[cc * 4 + 0], lo[cc * 4 + 0]);
            bsplit(v1, hi[cc * 4 + 1], lo[cc * 4 + 1]);
            bsplit(v2, hi[cc * 4 + 2], lo[cc * 4 + 2]);
            bsplit(v3, hi[cc * 4 + 3], lo[cc * 4 + 3]);
        }
        *(uint4*)(smem + A1_HI + (row * P1 + u * 8) * 2) = *(uint4*)hi;
        *(uint4*)(smem + A1_LO + (row * P1 + u * 8) * 2) = *(uint4*)lo;
    }

    // ---- layer 1 MMAs: 4 chunks of K=32 ----
    u32 a_row = (u32)(wg * 16 + (lane & 15));
    u32 a_col = (u32)((lane >> 4) * 8);
    u32 aH = sb + A1_HI + (a_row * P1 + a_col) * 2;
    u32 aL = sb + A1_LO + (a_row * P1 + a_col) * 2;
    int g = lane >> 3;
    u32 brow = (u32)(jh * 128 + (g >> 1) * 8 + (lane & 7));
    u32 bcol = (u32)((g & 1) * 8);
    u32 bH4 = sb + B1_HI + (brow * PB1 + bcol) * 2;
    u32 bL4 = sb + B1_LO + (brow * PB1 + bcol) * 2;

    float bj1v[16][2];
#pragma unroll
    for (int jt = 0; jt < 16; jt++) {
        int jg = jh * 128 + jt * 8 + (lane & 3) * 2;
        bj1v[jt][0] = __ldg(&b1[jg]);
        bj1v[jt][1] = __ldg(&b1[jg + 1]);
    }

    float acc[16][4];
#pragma unroll
    for (int t = 0; t < 16; t++)
#pragma unroll
        for (int q = 0; q < 4; q++) acc[t][q] = 0.f;

#pragma unroll
    for (int kc = 0; kc < 4; kc++) {
        for (int idx = tid; idx < 256 * 4; idx += 256) {
            int row = idx >> 2, u = idx & 3;
            long koff = kc * 32 + u * 8;
            *(uint4*)(smem + B1_HI + (row * PB1 + u * 8) * 2) = *(const uint4*)(g_w1h + (long)row * DIM + koff);
            *(uint4*)(smem + B1_LO + (row * PB1 + u * 8) * 2) = *(const uint4*)(g_w1l + (long)row * DIM + koff);
        }
        __syncthreads();
#pragma unroll
        for (int ks = 0; ks < 2; ks++) {
            u32 ah[4], al[4];
            ldsm4(ah, aH + kc * 64 + ks * 32);
            ldsm4(al, aL + kc * 64 + ks * 32);
#pragma unroll
            for (int jp = 0; jp < 8; jp++) {
                u32 bh[4], bl[4];
                ldsm4(bh, bH4 + jp * (16 * PB1 * 2) + ks * 32);
                ldsm4(bl, bL4 + jp * (16 * PB1 * 2) + ks * 32);
                mma16816(acc[2 * jp],     ah, &bh[0]);
                mma16816(acc[2 * jp],     ah, &bl[0]);
                mma16816(acc[2 * jp],     al, &bh[0]);
                mma16816(acc[2 * jp + 1], ah, &bh[2]);
                mma16816(acc[2 * jp + 1], ah, &bl[2]);
                mma16816(acc[2 * jp + 1], al, &bh[2]);
            }
        }
        __syncthreads();
    }

    // ---- layer 1 epilogue: bias + GELU, split, write hid tile to smem ----
    {
        int r0 = wg * 16 + (lane >> 2);
        int r1 = r0 + 8;
#pragma unroll
        for (int jt = 0; jt < 16; jt++) {
            int jg = jh * 128 + jt * 8 + (lane & 3) * 2;
#pragma unroll
            for (int half = 0; half < 2; half++) {
                int r = half ? r1 : r0;
                float a0 = acc[jt][half * 2 + 0] + bj1v[jt][0];
                float a1 = acc[jt][half * 2 + 1] + bj1v[jt][1];
                float y0 = 0.5f * a0 * (1.0f + erff(a0 * 0.7071067811865476f));
                float y1 = 0.5f * a1 * (1.0f + erff(a1 * 0.7071067811865476f));
                __nv_bfloat162 ph, pl;
                bsplit(y0, ph.x, pl.x);
                bsplit(y1, ph.y, pl.y);
                *(u32*)(smem + H_HI + (r * P2 + jg) * 2) = *(u32*)&ph;
                *(u32*)(smem + H_LO + (r * P2 + jg) * 2) = *(u32*)&pl;
            }
        }
    }
    __syncthreads();

    // ---- layer 2 MMAs: 4 chunks of K=64 ----
    u32 aH2 = sb + H_HI + (a_row * P2 + a_col) * 2;
    u32 aL2 = sb + H_LO + (a_row * P2 + a_col) * 2;
    u32 brow2 = (u32)(jh * 64 + (g >> 1) * 8 + (lane & 7));
    u32 bH2 = sb + B2_HI + (brow2 * PB2 + bcol) * 2;
    u32 bL2 = sb + B2_LO + (brow2 * PB2 + bcol) * 2;

    float acc2[8][4];
#pragma unroll
    for (int t = 0; t < 8; t++)
#pragma unroll
        for (int q = 0; q < 4; q++) acc2[t][q] = 0.f;

#pragma unroll
    for (int kc = 0; kc < 4; kc++) {
        for (int idx = tid; idx < 128 * 8; idx += 256) {
            int row = idx >> 3, u = idx & 7;
            long koff = kc * 64 + u * 8;
            *(uint4*)(smem + B2_HI + (row * PB2 + u * 8) * 2) = *(const uint4*)(g_w2h + (long)row * HID + koff);
            *(uint4*)(smem + B2_LO + (row * PB2 + u * 8) * 2) = *(const uint4*)(g_w2l + (long)row * HID + koff);
        }
        __syncthreads();
#pragma unroll
        for (int ks = 0; ks < 4; ks++) {
            u32 ah[4], al[4];
            ldsm4(ah, aH2 + kc * 128 + ks * 32);
            ldsm4(al, aL2 + kc * 128 + ks * 32);
#pragma unroll
            for (int jp = 0; jp < 4; jp++) {
                u32 bh[4], bl[4];
                ldsm4(bh, bH2 + jp * (16 * PB2 * 2) + ks * 32);
                ldsm4(bl, bL2 + jp * (16 * PB2 * 2) + ks * 32);
                mma16816(acc2[2 * jp],     ah, &bh[0]);
                mma16816(acc2[2 * jp],     ah, &bl[0]);
                mma16816(acc2[2 * jp],     al, &bh[0]);
                mma16816(acc2[2 * jp + 1], ah, &bh[2]);
                mma16816(acc2[2 * jp + 1], ah, &bl[2]);
                mma16816(acc2[2 * jp + 1], al, &bh[2]);
            }
        }
        __syncthreads();
    }

    // ---- layer 2 epilogue: bias, store out ----
    long n0 = nbase + wg * 16 + (lane >> 2);
    long n1 = n0 + 8;
#pragma unroll
    for (int jt = 0; jt < 8; jt++) {
        int jg = jh * 64 + jt * 8 + (lane & 3) * 2;
        float bj0 = __ldg(&b2[jg]), bj1 = __ldg(&b2[jg + 1]);
        if (n0 < N_NODES) {
            float2 v = make_float2(acc2[jt][0] + bj0, acc2[jt][1] + bj1);
            *(float2*)(out + n0 * DIM + jg) = v;
        }
        if (n1 < N_NODES) {
            float2 v = make_float2(acc2[jt][2] + bj0, acc2[jt][3] + bj1);
            *(float2*)(out + n1 * DIM + jg) = v;
        }
    }
}

// ---------------- launch ----------------------------------------------------
extern "C" void kernel_launch(void* const* d_in, const int* in_sizes, int n_in,
                              void* d_out, int out_size) {
    const float* x   = (const float*)d_in[0];
    const float* rep = (const float*)d_in[1];
    const int*   src = (const int*)d_in[2];
    const int*   dst = (const int*)d_in[3];
    const float* w1  = (const float*)d_in[4];
    const float* b1  = (const float*)d_in[5];
    const float* w2  = (const float*)d_in[6];
    const float* b2  = (const float*)d_in[7];
    float* out = (float*)d_out;

    static int smem_set = 0;
    if (!smem_set) {
        cudaFuncSetAttribute(ffn_fused, cudaFuncAttributeMaxDynamicSharedMemorySize, FF_SMEM);
        smem_set = 1;
    }

    float* ha;
    __half *h16a, *h16b;
    cudaGetSymbolAddress((void**)&ha,   g_ha);
    cudaGetSymbolAddress((void**)&h16a, g_h16a);
    cudaGetSymbolAddress((void**)&h16b, g_h16b);

    // CSR build (index-only, fused scan)
    init_kernel<<<(N_NODES + 255) / 256, 256>>>(src, w1, w2);
    deg_hist_kernel<<<N_EDGES / 256, 256>>>(src, dst);
    scan_kernel<<<SCAN_B, 1024>>>();
    fill_kernel<<<N_EDGES / 256, 256>>>(src, dst);

    // forward rotation (pre-scaled by rsq(deg)) -> fp16 rows
    rot_kernel<<<(N_NODES * DIM) / 256, 256>>>(x, rep, h16a);

    // message passing: plain-sum gathers with boundary scales
    gather_h2h<<<(N_NODES * 32) / 256, 256>>>(h16a, h16b);
    gather_h2f<<<(N_NODES * 32) / 256, 256>>>(h16b, ha);

    // fused FFN (rot_t + layer1 + gelu + layer2, hid never leaves smem)
    ffn_fused<<<(N_NODES + 63) / 64, 256, FF_SMEM>>>(rep, b1, b2, out);
}